// round 15
// baseline (speedup 1.0000x reference)
#include <cuda_runtime.h>
#include <math.h>

#define NB     4096
#define ND     4096
#define NCLS   10
#define CEB    32           // K1 blocks that also do CE (128 rows each)

// Scratch (no allocations allowed -> __device__ globals)
__device__ float  g_r[NB];              // 1/||g_i - min_i||
__device__ float  g_mn[NB];             // row min
__device__ int    g_cls[NB];            // argmax class
__device__ int    g_bpos[NB];           // within-(ce-block,class) rank
__device__ int    g_bcnt[CEB][NCLS];    // per-ce-block class counts (plain stores)
__device__ double g_cepart[CEB];        // per-ce-block CE partials (plain stores)

// ===== K1: per-row min/sum/sumsq; blocks 0..31 also CE (float path, lean regs)
__global__ void __launch_bounds__(128) k_main(
    const float* __restrict__ grad, const float* __restrict__ outputs,
    const int* __restrict__ y, float* __restrict__ out) {
    int row = blockIdx.x;
    int tid = threadIdx.x;
    const float4* gp = (const float4*)grad + (size_t)row * (ND / 4);

    float mn = 3.0e38f, sum = 0.f, sq = 0.f;
#pragma unroll
    for (int j = 0; j < 8; j++) {
        float4 v = gp[j * 128 + tid];
        mn  = fminf(mn, fminf(fminf(v.x, v.y), fminf(v.z, v.w)));
        sum += (v.x + v.y) + (v.z + v.w);
        sq  += (v.x * v.x + v.y * v.y) + (v.z * v.z + v.w * v.w);
    }
#pragma unroll
    for (int o = 16; o; o >>= 1) {
        mn   = fminf(mn, __shfl_xor_sync(0xffffffffu, mn, o));
        sum += __shfl_xor_sync(0xffffffffu, sum, o);
        sq  += __shfl_xor_sync(0xffffffffu, sq, o);
    }
    __shared__ float smn[4], ssum[4], ssq[4];
    int w = tid >> 5;
    if ((tid & 31) == 0) { smn[w] = mn; ssum[w] = sum; ssq[w] = sq; }
    __syncthreads();
    if (tid == 0) {
        mn = fminf(fminf(smn[0], smn[1]), fminf(smn[2], smn[3]));
        double s = (double)ssum[0] + ssum[1] + ssum[2] + ssum[3];
        double q = (double)ssq[0] + ssq[1] + ssq[2] + ssq[3];
        double mnd = (double)mn;
        // sum of (g-min)^2 ; the (max-min) scale cancels in cosine similarity
        double var = q - 2.0 * mnd * s + (double)ND * mnd * mnd;
        g_r[row]  = (float)(1.0 / sqrt(var));
        g_mn[row] = mn;
        if (row == 0) out[0] = 0.0f;  // K2 accumulates via atomicAdd
    }

    // ---- CE / argmax / per-block class counts (blocks 0..31, 1 row/thread)
    if (blockIdx.x < CEB) {
        __shared__ int    cnt[NCLS];
        __shared__ double ced[4];
        if (tid < NCLS) cnt[tid] = 0;
        __syncthreads();

        int rr = blockIdx.x * 128 + tid;
        const float* o = outputs + rr * NCLS;
        float vals[NCLS];
        float mx = o[0]; int am = 0;
        vals[0] = mx;
#pragma unroll
        for (int c = 1; c < NCLS; c++) {
            float v = o[c]; vals[c] = v;
            if (v > mx) { mx = v; am = c; }  // strict > == first max (jnp.argmax)
        }
        float e = 0.f;
#pragma unroll
        for (int c = 0; c < NCLS; c++) e += __expf(vals[c] - mx);
        float lse = mx + logf(e);            // fp32: ~1e-7 rel per term, ample
        double local = (double)(lse - vals[y[rr]]);

        g_cls[rr]  = am;
        g_bpos[rr] = atomicAdd(&cnt[am], 1); // smem atomic (block-local)

#pragma unroll
        for (int off = 16; off; off >>= 1)
            local += __shfl_xor_sync(0xffffffffu, local, off);
        if ((tid & 31) == 0) ced[tid >> 5] = local;
        __syncthreads();
        if (tid < NCLS) g_bcnt[blockIdx.x][tid] = cnt[tid];
        if (tid == 0)
            g_cepart[blockIdx.x] = ced[0] + ced[1] + ced[2] + ced[3];
    }
}

// ===== K2 (fused): class column sums + local t_c + squared-norm fold
// grid (32 stripes, NCLS) x 256. Block covers 128 cols (32 float4-cols) with
// 8 row-groups; smem combine yields the COMPLETE S_c[col]; t_c computed
// in-block during the gather (identical across a class's 32 blocks).
__global__ void __launch_bounds__(256) k_fused(
    const float* __restrict__ grad, float* __restrict__ out) {
    int tid  = threadIdx.x;
    int c    = blockIdx.y;
    int c4   = tid & 31;             // float4-column within the 128-col stripe
    int grp  = tid >> 5;             // 8 row-groups (== warp id)
    int col  = blockIdx.x * 128 + c4 * 4;
    int lane = tid & 31;

    __shared__ int    base[CEB + 1];
    __shared__ int    sidx[NB];      // 16 KB
    __shared__ float  sr[NB];        // 16 KB
    __shared__ double tcw[8];
    __shared__ double stc;
    __shared__ int    snc[NCLS];
    __shared__ double sce;

    // parallel prefix over per-ce-block counts (one warp, shfl scan)
    if (tid < CEB) {
        int v = g_bcnt[tid][c];
#pragma unroll
        for (int o = 1; o < 32; o <<= 1) {
            int nvec = __shfl_up_sync(0xffffffffu, v, o);
            if (lane >= o) v += nvec;
        }
        base[tid + 1] = v;           // inclusive scan
        if (tid == 0) base[0] = 0;
    }
    // designated block: stage CE total + class counts for the loss base
    if (blockIdx.x == 0 && c == 0) {
        if (tid >= 64 && tid < 64 + NCLS) {
            int k = tid - 64, acc = 0;
            for (int b = 0; b < CEB; b++) acc += g_bcnt[b][k];
            snc[k] = acc;
        }
        if (tid == 96) {
            double ce = 0.0;
            for (int b = 0; b < CEB; b++) ce += g_cepart[b];
            sce = ce;
        }
    }
    __syncthreads();
    int cnt = base[CEB];             // n_c

    // gather the class row list; accumulate t_c = sum(mn_i * r_i) alongside
    double tcp = 0.0;
    for (int r = tid; r < NB; r += 256) {
        if (g_cls[r] == c) {
            int p = base[r >> 7] + g_bpos[r];   // 128 rows per ce-block
            float rv = g_r[r];
            sidx[p] = r;
            sr[p]   = rv;
            tcp += (double)g_mn[r] * (double)rv;
        }
    }
#pragma unroll
    for (int o = 16; o; o >>= 1)
        tcp += __shfl_xor_sync(0xffffffffu, tcp, o);
    if (lane == 0) tcw[grp] = tcp;
    __syncthreads();
    if (tid == 0) {
        double t = 0.0;
#pragma unroll
        for (int i = 0; i < 8; i++) t += tcw[i];
        stc = t;
    }

    // weighted column sum, rows strided by group: S_c[col] over p ≡ grp (mod 8)
    float4 acc = make_float4(0.f, 0.f, 0.f, 0.f);
    int i = grp;
    for (; i + 24 < cnt; i += 32) {
        const float4 v0 = *(const float4*)(grad + (size_t)sidx[i]      * ND + col);
        const float4 v1 = *(const float4*)(grad + (size_t)sidx[i + 8]  * ND + col);
        const float4 v2 = *(const float4*)(grad + (size_t)sidx[i + 16] * ND + col);
        const float4 v3 = *(const float4*)(grad + (size_t)sidx[i + 24] * ND + col);
        float r0 = sr[i], r1 = sr[i + 8], r2 = sr[i + 16], r3 = sr[i + 24];
        acc.x = fmaf(r0, v0.x, acc.x); acc.y = fmaf(r0, v0.y, acc.y);
        acc.z = fmaf(r0, v0.z, acc.z); acc.w = fmaf(r0, v0.w, acc.w);
        acc.x = fmaf(r1, v1.x, acc.x); acc.y = fmaf(r1, v1.y, acc.y);
        acc.z = fmaf(r1, v1.z, acc.z); acc.w = fmaf(r1, v1.w, acc.w);
        acc.x = fmaf(r2, v2.x, acc.x); acc.y = fmaf(r2, v2.y, acc.y);
        acc.z = fmaf(r2, v2.z, acc.z); acc.w = fmaf(r2, v2.w, acc.w);
        acc.x = fmaf(r3, v3.x, acc.x); acc.y = fmaf(r3, v3.y, acc.y);
        acc.z = fmaf(r3, v3.z, acc.z); acc.w = fmaf(r3, v3.w, acc.w);
    }
    for (; i < cnt; i += 8) {
        const float4 v = *(const float4*)(grad + (size_t)sidx[i] * ND + col);
        float r = sr[i];
        acc.x = fmaf(r, v.x, acc.x); acc.y = fmaf(r, v.y, acc.y);
        acc.z = fmaf(r, v.z, acc.z); acc.w = fmaf(r, v.w, acc.w);
    }

    // combine the 8 row-groups -> complete S_c for these 128 columns
    __shared__ float4 sp[8][32];
    sp[grp][c4] = acc;
    __syncthreads();

    __shared__ double sd;
    if (tid < 32) {
        float4 S = sp[0][tid];
#pragma unroll
        for (int g2 = 1; g2 < 8; g2++) {
            float4 v = sp[g2][tid];
            S.x += v.x; S.y += v.y; S.z += v.z; S.w += v.w;
        }
        double tcv = stc;
        double x = (double)S.x - tcv, yv = (double)S.y - tcv;
        double z = (double)S.z - tcv, w  = (double)S.w - tcv;
        double local = x * x + yv * yv + z * z + w * w;
#pragma unroll
        for (int o = 16; o; o >>= 1)
            local += __shfl_xor_sync(0xffffffffu, local, o);
        if (tid == 0) sd = local;
    }
    __syncthreads();
    if (tid == 0) {
        // loss = ce/B + P/B + 0.5 - s2/(2B); each block folds its s2 share,
        // the designated block also folds the base. out pre-zeroed by K1.
        double contrib = -sd / (2.0 * (double)NB);
        if (blockIdx.x == 0 && c == 0) {
            double P = 0.0;
            for (int k = 0; k < NCLS; k++)
                P += 0.5 * (double)snc[k] * (double)(snc[k] - 1);
            contrib += sce / (double)NB + P / (double)NB + 0.5;
        }
        atomicAdd(out, (float)contrib);
    }
}

extern "C" void kernel_launch(void* const* d_in, const int* in_sizes, int n_in,
                              void* d_out, int out_size) {
    (void)out_size;
    const float* outputs = nullptr;
    const float* grad    = nullptr;
    const int*   y       = nullptr;
    for (int i = 0; i < n_in; i++) {
        if      (in_sizes[i] == NB * ND)   grad    = (const float*)d_in[i];
        else if (in_sizes[i] == NB * NCLS) outputs = (const float*)d_in[i];
        else if (in_sizes[i] == NB)        y       = (const int*)d_in[i];
    }
    float* out = (float*)d_out;

    k_main<<<NB, 128>>>(grad, outputs, y, out);
    k_fused<<<dim3(32, NCLS), 256>>>(grad, out);
}

// round 16
// speedup vs baseline: 1.2856x; 1.2856x over previous
#include <cuda_runtime.h>
#include <math.h>

#define NB     4096
#define ND     4096
#define NCLS   10

// Scratch (no allocations -> __device__ globals). Static init covers launch 1;
// K2's last-ticket block re-zeroes the accumulators for every later launch.
__device__ int          g_cnt[NCLS] = {0};        // class counts (K1 atomics)
__device__ double       g_tc[NCLS]  = {0.0};      // sum over class of mn_i*r_i
__device__ double       g_ce        = 0.0;        // CE sum
__device__ unsigned int g_tick      = 0u;         // K2 completion ticket
__device__ int          g_sidx[NCLS][NB];         // class-compacted row indices
__device__ float        g_sr[NCLS][NB];           // class-compacted weights r_i

// ===== K1: per-row min/sum/sumsq ; tid0 classifies + CE + compacted scatter
__global__ void __launch_bounds__(128) k_main(
    const float* __restrict__ grad, const float* __restrict__ outputs,
    const int* __restrict__ y, float* __restrict__ out) {
    int row = blockIdx.x;
    int tid = threadIdx.x;

    // prefetch this row's logits (consumed by tid0 after the reduction sync)
    __shared__ float so[NCLS];
    if (tid < NCLS) so[tid] = outputs[row * NCLS + tid];
    if (row == 0 && tid == 0) { out[0] = 0.0f; g_tick = 0u; }

    const float4* gp = (const float4*)grad + (size_t)row * (ND / 4);
    float mn = 3.0e38f, sum = 0.f, sq = 0.f;
#pragma unroll
    for (int j = 0; j < 8; j++) {
        float4 v = gp[j * 128 + tid];
        mn  = fminf(mn, fminf(fminf(v.x, v.y), fminf(v.z, v.w)));
        sum += (v.x + v.y) + (v.z + v.w);
        sq  += (v.x * v.x + v.y * v.y) + (v.z * v.z + v.w * v.w);
    }
#pragma unroll
    for (int o = 16; o; o >>= 1) {
        mn   = fminf(mn, __shfl_xor_sync(0xffffffffu, mn, o));
        sum += __shfl_xor_sync(0xffffffffu, sum, o);
        sq  += __shfl_xor_sync(0xffffffffu, sq, o);
    }
    __shared__ float smn[4], ssum[4], ssq[4];
    int w = tid >> 5;
    if ((tid & 31) == 0) { smn[w] = mn; ssum[w] = sum; ssq[w] = sq; }
    __syncthreads();
    if (tid == 0) {
        mn = fminf(fminf(smn[0], smn[1]), fminf(smn[2], smn[3]));
        double s = (double)ssum[0] + ssum[1] + ssum[2] + ssum[3];
        double q = (double)ssq[0] + ssq[1] + ssq[2] + ssq[3];
        double mnd = (double)mn;
        // sum of (g-min)^2 ; the (max-min) scale cancels in cosine similarity
        double var = q - 2.0 * mnd * s + (double)ND * mnd * mnd;
        float rinv = (float)(1.0 / sqrt(var));

        // argmax (strict > == first max, matching jnp.argmax) + fp32 CE
        float mx = so[0]; int am = 0;
#pragma unroll
        for (int c = 1; c < NCLS; c++) {
            float v = so[c];
            if (v > mx) { mx = v; am = c; }
        }
        float e = 0.f;
#pragma unroll
        for (int c = 0; c < NCLS; c++) e += __expf(so[c] - mx);
        float lse = mx + logf(e);           // fp32: ~1e-7 rel per term, ample

        // compacted scatter: order within class is irrelevant to S_c / t_c
        int pos = atomicAdd(&g_cnt[am], 1);
        g_sidx[am][pos] = row;
        g_sr[am][pos]   = rinv;
        atomicAdd(&g_tc[am], mnd * (double)rinv);
        atomicAdd(&g_ce, (double)(lse - so[y[row]]));
    }
}

// ===== K2: pure streaming class column sums + squared-norm fold
// grid (32 stripes, NCLS) x 256. Block covers 128 cols (32 float4-cols) with
// 8 row-groups over the precompacted class list; smem combine yields the
// COMPLETE S_c[col]; block folds -sum((S-t_c)^2)/(2B) into out.
// Last-ticket block re-zeroes the K1 accumulators for the next graph replay.
__global__ void __launch_bounds__(256) k_fused(
    const float* __restrict__ grad, float* __restrict__ out) {
    int tid  = threadIdx.x;
    int c    = blockIdx.y;
    int c4   = tid & 31;             // float4-column within the 128-col stripe
    int grp  = tid >> 5;             // 8 row-groups (== warp id)
    int col  = blockIdx.x * 128 + c4 * 4;

    int n = g_cnt[c];                // broadcast load (uniform)
    const int*   idx = g_sidx[c];
    const float* wv  = g_sr[c];

    // weighted column sum over rows p ≡ grp (mod 8) of the class list
    float4 acc = make_float4(0.f, 0.f, 0.f, 0.f);
    int i = grp;
    for (; i + 24 < n; i += 32) {
        int   i0 = __ldg(idx + i),      i1 = __ldg(idx + i + 8);
        int   i2 = __ldg(idx + i + 16), i3 = __ldg(idx + i + 24);
        float r0 = __ldg(wv + i),       r1 = __ldg(wv + i + 8);
        float r2 = __ldg(wv + i + 16),  r3 = __ldg(wv + i + 24);
        const float4 v0 = *(const float4*)(grad + (size_t)i0 * ND + col);
        const float4 v1 = *(const float4*)(grad + (size_t)i1 * ND + col);
        const float4 v2 = *(const float4*)(grad + (size_t)i2 * ND + col);
        const float4 v3 = *(const float4*)(grad + (size_t)i3 * ND + col);
        acc.x = fmaf(r0, v0.x, acc.x); acc.y = fmaf(r0, v0.y, acc.y);
        acc.z = fmaf(r0, v0.z, acc.z); acc.w = fmaf(r0, v0.w, acc.w);
        acc.x = fmaf(r1, v1.x, acc.x); acc.y = fmaf(r1, v1.y, acc.y);
        acc.z = fmaf(r1, v1.z, acc.z); acc.w = fmaf(r1, v1.w, acc.w);
        acc.x = fmaf(r2, v2.x, acc.x); acc.y = fmaf(r2, v2.y, acc.y);
        acc.z = fmaf(r2, v2.z, acc.z); acc.w = fmaf(r2, v2.w, acc.w);
        acc.x = fmaf(r3, v3.x, acc.x); acc.y = fmaf(r3, v3.y, acc.y);
        acc.z = fmaf(r3, v3.z, acc.z); acc.w = fmaf(r3, v3.w, acc.w);
    }
    for (; i < n; i += 8) {
        int   ii = __ldg(idx + i);
        float r  = __ldg(wv + i);
        const float4 v = *(const float4*)(grad + (size_t)ii * ND + col);
        acc.x = fmaf(r, v.x, acc.x); acc.y = fmaf(r, v.y, acc.y);
        acc.z = fmaf(r, v.z, acc.z); acc.w = fmaf(r, v.w, acc.w);
    }

    // combine the 8 row-groups -> complete S_c for these 128 columns
    __shared__ float4 sp[8][32];
    sp[grp][c4] = acc;
    __syncthreads();

    __shared__ double sd;
    if (tid < 32) {
        float4 S = sp[0][tid];
#pragma unroll
        for (int g2 = 1; g2 < 8; g2++) {
            float4 v = sp[g2][tid];
            S.x += v.x; S.y += v.y; S.z += v.z; S.w += v.w;
        }
        double tcv = g_tc[c];
        double x = (double)S.x - tcv, yv = (double)S.y - tcv;
        double z = (double)S.z - tcv, w  = (double)S.w - tcv;
        double local = x * x + yv * yv + z * z + w * w;
#pragma unroll
        for (int o = 16; o; o >>= 1)
            local += __shfl_xor_sync(0xffffffffu, local, o);
        if (tid == 0) sd = local;
    }
    __syncthreads();

    if (tid == 0) {
        // loss = ce/B + P/B + 0.5 - s2/(2B); each block folds its s2 share,
        // the designated block also folds the base. out pre-zeroed by K1.
        double contrib = -sd / (2.0 * (double)NB);
        if (blockIdx.x == 0 && c == 0) {
            double ce = g_ce;
            double P  = 0.0;
            for (int k = 0; k < NCLS; k++) {
                double nc = (double)g_cnt[k];
                P += 0.5 * nc * (nc - 1.0);
            }
            contrib += ce / (double)NB + P / (double)NB + 0.5;
        }
        atomicAdd(out, (float)contrib);

        // last block cleans the K1 accumulators for the next replay
        // (every block's reads of g_cnt/g_tc/g_ce precede its ticket add)
        if (atomicAdd(&g_tick, 1u) == 32 * NCLS - 1) {
            for (int k = 0; k < NCLS; k++) { g_cnt[k] = 0; g_tc[k] = 0.0; }
            g_ce = 0.0;
        }
    }
}

extern "C" void kernel_launch(void* const* d_in, const int* in_sizes, int n_in,
                              void* d_out, int out_size) {
    (void)out_size;
    const float* outputs = nullptr;
    const float* grad    = nullptr;
    const int*   y       = nullptr;
    for (int i = 0; i < n_in; i++) {
        if      (in_sizes[i] == NB * ND)   grad    = (const float*)d_in[i];
        else if (in_sizes[i] == NB * NCLS) outputs = (const float*)d_in[i];
        else if (in_sizes[i] == NB)        y       = (const int*)d_in[i];
    }
    float* out = (float*)d_out;

    k_main<<<NB, 128>>>(grad, outputs, y, out);
    k_fused<<<dim3(32, NCLS), 256>>>(grad, out);
}